// round 13
// baseline (speedup 1.0000x reference)
#include <cuda_runtime.h>
#include <math.h>

#define Bb 8
#define Cc 16
#define WD 192
#define HT 192
#define NPIX (WD*HT)
#define Hh 4
#define HID 16
#define OCH 32
#define W2 214
#define SDIM 144
#define CSTRIDE 674

typedef unsigned long long ull;

// ---------------- packed f32x2 helpers ----------------
__device__ __forceinline__ ull pk2(float lo, float hi) {
    ull u;
    asm("mov.b64 %0, {%1, %2};" : "=l"(u) : "f"(lo), "f"(hi));
    return u;
}
__device__ __forceinline__ void upk2(ull u, float& lo, float& hi) {
    asm("mov.b64 {%0, %1}, %2;" : "=f"(lo), "=f"(hi) : "l"(u));
}
__device__ __forceinline__ ull ffma2(ull a, ull b, ull c) {
    ull d;
    asm("fma.rn.f32x2 %0, %1, %2, %3;" : "=l"(d) : "l"(a), "l"(b), "l"(c));
    return d;
}
// load a (qy, qy+1) pair at compile-time offset OFF from an even-word base+qy
template<int OFF>
__device__ __forceinline__ ull ldb(const float* p, int qy) {
    if constexpr ((OFF & 1) == 0)
        return *(const ull*)(p + qy + OFF);
    else
        return pk2(p[qy + OFF], p[qy + OFF + 1]);
}

// ---------------- device scratch ----------------
__device__ float g_Wq[Hh][HID][SDIM];
__device__ float g_Wk[Hh][128][SDIM];
__device__ float g_Wv[Hh][128][SDIM];
__device__ float g_W2[Bb][Hh][OCH][SDIM];
__device__ float g_bnsum[OCH];
__device__ float g_bnsq[OCH];

// correlation tables: [bh][pair=c1*16+c2][lag dd=ix*5+iy]
__device__ float g_F [32][256][25];
__device__ float g_SxS[2][32][256][25];
__device__ float g_SyS[2][32][256][25];
__device__ float g_Cn [4][32][256][25];

__constant__ int c_shift[4] = {1, 2, 4, 8};
__constant__ int c_off[8]   = {0, 1, 2, 5, 8, 7, 6, 3};

// ---------------- kernel 1: fold blend kernels into effective conv weights ----------------
__global__ void k_prep(const float* __restrict__ wq, const float* __restrict__ wk,
                       const float* __restrict__ wv, const float* __restrict__ sum_w) {
    int h = blockIdx.x;
    int t = threadIdx.x;
    __shared__ float wcen[Cc][9];
    __shared__ float wsur[Cc][8][9];

    if (t < Cc * 9) {
        int c = t / 9, d = t % 9;
        float sw = sum_w[h * Cc + c];
        float su_f = (d == 4) ? 0.125f : (7.0f / 64.0f);
        float ce   = (d == 4) ? 1.0f : 0.0f;
        wcen[c][d] = su_f * (1.0f - sw) + ce * sw;
    }
    for (int idx = t; idx < Cc * 8 * 9; idx += 256) {
        int c = idx / 72;
        int k = (idx / 9) % 8;
        int d = idx % 9;
        float sw = sum_w[h * Cc + c];
        float delta = ((d == 4) ? 1.0f : 0.0f) + ((d == c_off[k]) ? -1.0f : 0.0f);
        float ce    = (d == 4) ? 1.0f : 0.0f;
        float k2w   = (delta - ce) * 1.125f + 0.125f;
        wsur[c][k][d] = delta * (1.0f - sw) + k2w * sw;
    }
    __syncthreads();

    for (int idx = t; idx < HID * SDIM; idx += 256) {
        int q = idx / SDIM, c = (idx % SDIM) / 9, d = idx % 9;
        g_Wq[h][q][c * 9 + d] = wq[(h * HID + q) * Cc + c] * wcen[c][d];
    }
    for (int idx = t; idx < 128 * SDIM; idx += 256) {
        int o = idx / SDIM, c = (idx % SDIM) / 9, d = idx % 9;
        float ak = 0.0f, av = 0.0f;
        #pragma unroll
        for (int k = 0; k < 8; k++) {
            float ws = wsur[c][k][d];
            ak = fmaf(wk[(h * 128 + o) * 128 + k * Cc + c], ws, ak);
            av = fmaf(wv[(h * 128 + o) * 128 + k * Cc + c], ws, av);
        }
        g_Wk[h][o][c * 9 + d] = ak;
        g_Wv[h][o][c * 9 + d] = av;
    }
}

// ---------------- kernel 2: zero accumulators ----------------
__global__ void k_zero() {
    const long per = 32L * 256 * 25;
    long stride = (long)gridDim.x * 256;
    long i0 = (long)blockIdx.x * 256 + threadIdx.x;
    for (long i = i0; i < per; i += stride) (&g_F[0][0][0])[i] = 0.0f;
    for (long i = i0; i < 2 * per; i += stride) (&g_SxS[0][0][0][0])[i] = 0.0f;
    for (long i = i0; i < 2 * per; i += stride) (&g_SyS[0][0][0][0])[i] = 0.0f;
    for (long i = i0; i < 4 * per; i += stride) (&g_Cn[0][0][0][0])[i] = 0.0f;
    if (blockIdx.x == 0 && threadIdx.x < OCH) {
        g_bnsum[threadIdx.x] = 0.0f;
        g_bnsq[threadIdx.x]  = 0.0f;
    }
}

// ---------------- kernel 3a: full-domain correlations, f32x2 packed over qy-pairs ----------------
// grid (24 x-chunks of 8 rows, Hh, Bb), 256 threads:
//   c2 = t&15, c1-group = (t>>4)&3 (4 c1 each), qy-quarter = t>>6 (48 qy = 24 pairs each).
template<int S>
__device__ __forceinline__ void corrF_body(const float* __restrict__ cb, float* __restrict__ Fbh,
                                           float* st, int xc, int t) {
    int c2 = t & 15;
    int c1b = ((t >> 4) & 3) * 4;
    int qq = t >> 6;

    ull acc[52];
    #pragma unroll
    for (int i = 0; i < 52; i++) acc[i] = 0ull;

    for (int qx = xc * 8; qx < xc * 8 + 8; qx++) {
        __syncthreads();
        for (int idx = t; idx < 16 * CSTRIDE; idx += 256) {
            int c = idx / CSTRIDE;
            int rm = idx - c * CSTRIDE;
            float v = 0.0f;
            if (rm < 672) {
                int k = rm / 224, j = rm - k * 224;
                int r = qx + k * S;
                int y = j - 16;
                if (r < WD && y >= 0 && y < HT)
                    v = cb[((size_t)c * WD + r) * HT + y];
            }
            st[idx] = v;
        }
        __syncthreads();

        const float* a0 = st + (c1b + 0) * CSTRIDE + 16;
        const float* a1 = st + (c1b + 1) * CSTRIDE + 16;
        const float* a2 = st + (c1b + 2) * CSTRIDE + 16;
        const float* a3 = st + (c1b + 3) * CSTRIDE + 16;
        const float* b0 = st + c2 * CSTRIDE + 16;
        const float* b1 = b0 + 224;
        const float* b2 = b1 + 224;
        #pragma unroll 2
        for (int qy = qq * 48; qy < qq * 48 + 48; qy += 2) {
            ull av0 = *(const ull*)(a0 + qy);
            ull av1 = *(const ull*)(a1 + qy);
            ull av2 = *(const ull*)(a2 + qy);
            ull av3 = *(const ull*)(a3 + qy);
            ull bv;
            #define CORR_LAG(L, PTR, OFF) \
                bv = ldb<(OFF)>(PTR, qy); \
                acc[0 * 13 + (L)] = ffma2(av0, bv, acc[0 * 13 + (L)]); \
                acc[1 * 13 + (L)] = ffma2(av1, bv, acc[1 * 13 + (L)]); \
                acc[2 * 13 + (L)] = ffma2(av2, bv, acc[2 * 13 + (L)]); \
                acc[3 * 13 + (L)] = ffma2(av3, bv, acc[3 * 13 + (L)]);
            CORR_LAG(0,  b0, 0)
            CORR_LAG(1,  b0, S)
            CORR_LAG(2,  b0, 2 * S)
            CORR_LAG(3,  b1, -2 * S)
            CORR_LAG(4,  b1, -S)
            CORR_LAG(5,  b1, 0)
            CORR_LAG(6,  b1, S)
            CORR_LAG(7,  b1, 2 * S)
            CORR_LAG(8,  b2, -2 * S)
            CORR_LAG(9,  b2, -S)
            CORR_LAG(10, b2, 0)
            CORR_LAG(11, b2, S)
            CORR_LAG(12, b2, 2 * S)
            #undef CORR_LAG
        }
    }
    #pragma unroll
    for (int i = 0; i < 4; i++) {
        float* dst = Fbh + ((c1b + i) * 16 + c2) * 25 + 12;
        #pragma unroll
        for (int l = 0; l < 13; l++) {
            float lo, hi;
            upk2(acc[i * 13 + l], lo, hi);
            atomicAdd(dst + l, lo + hi);
        }
    }
}

__global__ void __launch_bounds__(256) k_corrF(const float* __restrict__ cen) {
    __shared__ __align__(16) float st[16 * CSTRIDE];
    int xc = blockIdx.x, h = blockIdx.y, b = blockIdx.z;
    const float* cb = cen + (size_t)b * Cc * NPIX;
    float* Fbh = &g_F[b * Hh + h][0][0];
    int t = threadIdx.x;
    switch (h) {
        case 0:  corrF_body<1>(cb, Fbh, st, xc, t); break;
        case 1:  corrF_body<2>(cb, Fbh, st, xc, t); break;
        case 2:  corrF_body<4>(cb, Fbh, st, xc, t); break;
        default: corrF_body<8>(cb, Fbh, st, xc, t); break;
    }
}

// ---------------- kernel 3b: x-border strips ----------------
// grid (64 = side(2) x ychunk(4) x qslot(8), Hh, Bb); ONE fill per block.
__global__ void __launch_bounds__(256) k_stripx(const float* __restrict__ cen) {
    __shared__ float yw[16 * 401];
    int bx = blockIdx.x;
    int side = bx & 1, chunk = (bx >> 1) & 3, qslot = bx >> 3;
    int h = blockIdx.y, b = blockIdx.z;
    int s = c_shift[h];
    if (qslot >= s) return;
    int bh = b * Hh + h;
    int t = threadIdx.x;
    int c1 = t & 15, c2 = t >> 4;
    const float* cb = cen + (size_t)b * Cc * NPIX;
    int x0 = side ? (WD - s) : 0;
    int qx = x0 + qslot;
    int ybase = chunk * 48 - 16;

    for (int idx = t; idx < 16 * 401; idx += 256) {
        int c = idx / 401;
        int rm = idx - c * 401;
        float v = 0.0f;
        if (rm < 400) {
            int k = rm / 80, j = rm - k * 80;
            int r = qx + (k - 2) * s;
            int y = ybase + j;
            if (r >= 0 && r < WD && y >= 0 && y < HT)
                v = cb[((size_t)c * WD + r) * HT + y];
        }
        yw[idx] = v;
    }
    __syncthreads();

    float acc[25];
    #pragma unroll
    for (int i = 0; i < 25; i++) acc[i] = 0.0f;

    const float* ar = yw + c1 * 401 + 2 * 80 + 16;
    const float* bb = yw + c2 * 401 + 16;
    for (int jj = 0; jj < 48; jj++) {
        float a = ar[jj];
        #pragma unroll
        for (int ix = 0; ix < 5; ix++) {
            const float* br = bb + ix * 80 + jj;
            #pragma unroll
            for (int iy = 0; iy < 5; iy++)
                acc[ix * 5 + iy] = fmaf(a, br[(iy - 2) * s], acc[ix * 5 + iy]);
        }
    }
    float* dst = &g_SxS[side][bh][c1 * 16 + c2][0];
    #pragma unroll
    for (int i = 0; i < 25; i++) atomicAdd(dst + i, acc[i]);
}

// ---------------- shared body for y-strips ----------------
__device__ __forceinline__ void stripy_body(const float* __restrict__ cen, float* yw,
                                            int side, int chunk, int h, int b) {
    int s = c_shift[h];
    int bh = b * Hh + h;
    int t = threadIdx.x;
    int c1 = t & 15, c2 = t >> 4;
    const float* cb = cen + (size_t)b * Cc * NPIX;
    int y0 = side ? (HT - s) : 0;
    int jy0 = y0 - 2 * s;
    int qx0 = chunk * 12;
    int rows = 12 + 4 * s;
    int ww = 5 * s;
    int stride = rows * ww + 1;

    for (int idx = t; idx < 16 * stride; idx += 256) {
        int c = idx / stride;
        int rm = idx - c * stride;
        float v = 0.0f;
        if (rm < rows * ww) {
            int rr = rm / ww, j = rm - rr * ww;
            int r = qx0 - 2 * s + rr;
            int y = jy0 + j;
            if (r >= 0 && r < WD && y >= 0 && y < HT)
                v = cb[((size_t)c * WD + r) * HT + y];
        }
        yw[idx] = v;
    }
    __syncthreads();

    float acc[25];
    #pragma unroll
    for (int i = 0; i < 25; i++) acc[i] = 0.0f;

    const float* base1 = yw + c1 * stride;
    const float* base2 = yw + c2 * stride;
    for (int dx = 0; dx < 12; dx++) {
        const float* ar = base1 + (dx + 2 * s) * ww + 2 * s;
        for (int jj = 0; jj < s; jj++) {
            float a = ar[jj];
            #pragma unroll
            for (int ix = 0; ix < 5; ix++) {
                const float* br = base2 + (dx + ix * s) * ww + jj;
                #pragma unroll
                for (int iy = 0; iy < 5; iy++)
                    acc[ix * 5 + iy] = fmaf(a, br[iy * s], acc[ix * 5 + iy]);
            }
        }
    }
    float* dst = &g_SyS[side][bh][c1 * 16 + c2][0];
    #pragma unroll
    for (int i = 0; i < 25; i++) atomicAdd(dst + i, acc[i]);
}

// s<=4 (h=0..2): static smem 16*561 floats = 35.9KB -> high occupancy
__global__ void __launch_bounds__(256) k_stripy_small(const float* __restrict__ cen) {
    __shared__ float yw[16 * 561];
    stripy_body(cen, yw, blockIdx.x & 1, blockIdx.x >> 1, blockIdx.y, blockIdx.z);
}
// s=8 (h=3): dynamic smem 112.7KB
__global__ void __launch_bounds__(256) k_stripy_big(const float* __restrict__ cen) {
    extern __shared__ float yw[];
    stripy_body(cen, yw, blockIdx.x & 1, blockIdx.x >> 1, 3, blockIdx.z);
}

// ---------------- kernel 3d: corner patches ----------------
__global__ void __launch_bounds__(256) k_corner(const float* __restrict__ cen) {
    int bx = blockIdx.x;
    int corner = bx & 3, islot = bx >> 2;
    int cx = corner >> 1, cy = corner & 1;
    int h = blockIdx.y, b = blockIdx.z;
    int s = c_shift[h];
    if (islot >= s) return;
    int bh = b * Hh + h;
    int t = threadIdx.x;
    int c1 = t & 15, c2 = t >> 4;
    const float* cb = cen + (size_t)b * Cc * NPIX;
    int x0 = cx ? (WD - s) : 0;
    int y0 = cy ? (HT - s) : 0;

    float acc[25];
    #pragma unroll
    for (int i = 0; i < 25; i++) acc[i] = 0.0f;

    int qx = x0 + islot;
    for (int j = 0; j < s; j++) {
        int qy = y0 + j;
        float a = cb[((size_t)c1 * WD + qx) * HT + qy];
        #pragma unroll
        for (int ix = 0; ix < 5; ix++) {
            int bxx = qx + (ix - 2) * s;
            #pragma unroll
            for (int iy = 0; iy < 5; iy++) {
                int by = qy + (iy - 2) * s;
                float bv = (bxx >= 0 && bxx < WD && by >= 0 && by < HT)
                           ? cb[((size_t)c2 * WD + bxx) * HT + by] : 0.0f;
                acc[ix * 5 + iy] = fmaf(a, bv, acc[ix * 5 + iy]);
            }
        }
    }
    float* dst = &g_Cn[corner][bh][c1 * 16 + c2][0];
    #pragma unroll
    for (int i = 0; i < 25; i++) atomicAdd(dst + i, acc[i]);
}

// ---------------- kernel 3e: mirror fill F for dd<12 ----------------
__global__ void k_mirrorF() {
    int bh = blockIdx.x;
    int p = threadIdx.x;
    int cA = p >> 4, cB = p & 15;
    int ps = cB * 16 + cA;
    #pragma unroll
    for (int d = 0; d < 12; d++)
        g_F[bh][p][d] = g_F[bh][ps][24 - d];
}

// ---------------- kernel 4: per (b,h) attention head (assembles S from corr tables) ----------------
__global__ void __launch_bounds__(512) k_attn(const float* __restrict__ w_out) {
    extern __shared__ float pool[];
    float* S_sm  = pool;
    float* Wk_sm = pool + 20880;
    float* Wq_sm = pool + 39440;
    float* T_sm  = pool + 41744;
    float* G     = pool + 44048;
    float* M     = Wk_sm;
    __shared__ float nq[16], nk[128], red[512];

    int bh = blockIdx.x;
    int b = bh >> 2, h = bh & 3;
    int t = threadIdx.x;

    for (int idx = t; idx < SDIM * SDIM; idx += 512) {
        int r = idx / SDIM, c = idx - r * SDIM;
        int c1 = r / 9, d1 = r - c1 * 9;
        int c2 = c / 9, d2 = c - c2 * 9;
        int o1x = d1 / 3 - 1, o1y = d1 % 3 - 1;
        int o2x = d2 / 3 - 1, o2y = d2 % 3 - 1;
        int dd = (o2x - o1x + 2) * 5 + (o2y - o1y + 2);
        int p = c1 * 16 + c2;
        float v = g_F[bh][p][dd];
        if (o1x > 0)      v -= g_SxS[0][bh][p][dd];
        else if (o1x < 0) v -= g_SxS[1][bh][p][dd];
        if (o1y > 0)      v -= g_SyS[0][bh][p][dd];
        else if (o1y < 0) v -= g_SyS[1][bh][p][dd];
        if (o1x != 0 && o1y != 0) {
            int ci = ((o1x > 0) ? 0 : 2) + ((o1y > 0) ? 0 : 1);
            v += g_Cn[ci][bh][p][dd];
        }
        S_sm[r * 145 + c] = v;
    }
    for (int idx = t; idx < 128 * SDIM; idx += 512) {
        int r = idx / SDIM, c = idx - r * SDIM;
        Wk_sm[r * 145 + c] = (&g_Wk[h][0][0])[idx];
    }
    for (int idx = t; idx < 16 * SDIM; idx += 512)
        Wq_sm[idx] = (&g_Wq[h][0][0])[idx];
    __syncthreads();

    for (int g = t; g < 576; g += 512) {
        int q = g / 36, i0 = (g - q * 36) * 4;
        float a0 = 0.0f, a1 = 0.0f, a2 = 0.0f, a3 = 0.0f;
        const float* wqr = Wq_sm + q * SDIM;
        #pragma unroll 4
        for (int j = 0; j < SDIM; j++) {
            float wv = wqr[j];
            const float* sr = S_sm + j * 145 + i0;
            a0 = fmaf(wv, sr[0], a0);
            a1 = fmaf(wv, sr[1], a1);
            a2 = fmaf(wv, sr[2], a2);
            a3 = fmaf(wv, sr[3], a3);
        }
        float* tr = T_sm + q * SDIM + i0;
        tr[0] = a0; tr[1] = a1; tr[2] = a2; tr[3] = a3;
    }
    __syncthreads();

    if (t < 16) {
        float a = 0.0f;
        for (int i = 0; i < SDIM; i++)
            a = fmaf(T_sm[t * SDIM + i], Wq_sm[t * SDIM + i], a);
        nq[t] = fmaxf(sqrtf(fmaxf(a, 0.0f)), 1e-12f);
    }

    {
        int q = t >> 5, k0 = (t & 31) * 4;
        float a0 = 0.0f, a1 = 0.0f, a2 = 0.0f, a3 = 0.0f;
        const float* tq = T_sm + q * SDIM;
        const float* w0 = Wk_sm + (k0 + 0) * 145;
        const float* w1 = Wk_sm + (k0 + 1) * 145;
        const float* w2 = Wk_sm + (k0 + 2) * 145;
        const float* w3 = Wk_sm + (k0 + 3) * 145;
        #pragma unroll 4
        for (int i = 0; i < SDIM; i++) {
            float tv = tq[i];
            a0 = fmaf(tv, w0[i], a0);
            a1 = fmaf(tv, w1[i], a1);
            a2 = fmaf(tv, w2[i], a2);
            a3 = fmaf(tv, w3[i], a3);
        }
        G[q * 128 + k0 + 0] = a0;
        G[q * 128 + k0 + 1] = a1;
        G[q * 128 + k0 + 2] = a2;
        G[q * 128 + k0 + 3] = a3;
    }

    {
        int k = t & 127, g = t >> 7;
        const float* wk_r = Wk_sm + k * 145;
        float a = 0.0f;
        #pragma unroll 1
        for (int qd = 0; qd < 9; qd++) {
            int i0 = g * 36 + qd * 4;
            float r0 = 0.0f, r1 = 0.0f, r2 = 0.0f, r3 = 0.0f;
            const float* s0 = S_sm + (i0 + 0) * 145;
            const float* s1 = S_sm + (i0 + 1) * 145;
            const float* s2 = S_sm + (i0 + 2) * 145;
            const float* s3 = S_sm + (i0 + 3) * 145;
            #pragma unroll 4
            for (int j = 0; j < SDIM; j++) {
                float wv = wk_r[j];
                r0 = fmaf(s0[j], wv, r0);
                r1 = fmaf(s1[j], wv, r1);
                r2 = fmaf(s2[j], wv, r2);
                r3 = fmaf(s3[j], wv, r3);
            }
            a = fmaf(wk_r[i0 + 0], r0, a);
            a = fmaf(wk_r[i0 + 1], r1, a);
            a = fmaf(wk_r[i0 + 2], r2, a);
            a = fmaf(wk_r[i0 + 3], r3, a);
        }
        red[t] = a;
    }
    __syncthreads();
    if (t < 128) {
        float sum = red[t] + red[t + 128] + red[t + 256] + red[t + 384];
        nk[t] = fmaxf(sqrtf(fmaxf(sum, 0.0f)), 1e-12f);
    }
    __syncthreads();

    for (int idx = t; idx < 2048; idx += 512) {
        int q = idx >> 7, k = idx & 127;
        G[idx] = G[idx] / (nq[q] * nk[k] * 192.0f);
    }
    __syncthreads();

    float lsum = 0.0f;
    for (int idx = t; idx < 2048; idx += 512) lsum += G[idx];
    red[t] = lsum; __syncthreads();
    for (int st = 256; st > 0; st >>= 1) { if (t < st) red[t] += red[t + st]; __syncthreads(); }
    float mean = red[0] * (1.0f / 2048.0f);
    __syncthreads();
    float lss = 0.0f;
    for (int idx = t; idx < 2048; idx += 512) { float d = G[idx] - mean; lss = fmaf(d, d, lss); }
    red[t] = lss; __syncthreads();
    for (int st = 256; st > 0; st >>= 1) { if (t < st) red[t] += red[t + st]; __syncthreads(); }
    float var = red[0] * (1.0f / 2048.0f);
    float iscale = rsqrtf(var + 1e-5f);
    __syncthreads();
    for (int idx = t; idx < 2048; idx += 512)
        G[idx] = (G[idx] - mean) * iscale;
    __syncthreads();

    int wid = t >> 5, lane = t & 31;
    {
        int q = wid;
        float m = -1e30f;
        for (int k = lane; k < 128; k += 32) m = fmaxf(m, G[q * 128 + k]);
        #pragma unroll
        for (int o = 16; o > 0; o >>= 1) m = fmaxf(m, __shfl_xor_sync(0xffffffffu, m, o));
        float ssum = 0.0f;
        for (int k = lane; k < 128; k += 32) {
            float e = expf(G[q * 128 + k] - m);
            G[q * 128 + k] = e;
            ssum += e;
        }
        #pragma unroll
        for (int o = 16; o > 0; o >>= 1) ssum += __shfl_xor_sync(0xffffffffu, ssum, o);
        float inv = 1.0f / ssum;
        for (int k = lane; k < 128; k += 32) G[q * 128 + k] *= inv;
    }
    __syncthreads();

    float mv[8];
    {
        #pragma unroll
        for (int r = 0; r < 8; r++) {
            int idx = t + r * 512;
            int o = idx >> 7, k = idx & 127;
            float a = 0.0f;
            #pragma unroll
            for (int q = 0; q < 16; q++)
                a = fmaf(w_out[o * 64 + h * 16 + q], G[q * 128 + k], a);
            mv[r] = a;
        }
    }
    __syncthreads();
    #pragma unroll
    for (int r = 0; r < 8; r++) M[t + r * 512] = mv[r];
    __syncthreads();

    for (int g = t; g < OCH * 36; g += 512) {
        int o = g / 36, i0 = (g - o * 36) * 4;
        float a0 = 0.0f, a1 = 0.0f, a2 = 0.0f, a3 = 0.0f;
        const float* mo = M + o * 128;
        #pragma unroll 4
        for (int k = 0; k < 128; k++) {
            float mvv = mo[k];
            const float* wvr = &g_Wv[h][k][i0];
            a0 = fmaf(mvv, wvr[0], a0);
            a1 = fmaf(mvv, wvr[1], a1);
            a2 = fmaf(mvv, wvr[2], a2);
            a3 = fmaf(mvv, wvr[3], a3);
        }
        float* w2r = &g_W2[b][h][o][i0];
        w2r[0] = a0; w2r[1] = a1; w2r[2] = a2; w2r[3] = a3;
    }
}

// ---------------- kernel 5: fused output conv (f32x2) + BN stats ----------------
__global__ void __launch_bounds__(256) k_out(const float* __restrict__ cen, float* __restrict__ out) {
    extern __shared__ float dsm[];
    float* insm = dsm;
    float* W2sm = dsm + Cc * 3 * W2;

    int xg = blockIdx.x, b = blockIdx.y;
    int t = threadIdx.x;
    int ty = t & 31, to = t >> 5;
    const float* cb = cen + (size_t)b * Cc * NPIX;

    for (int xr = 0; xr < 4; xr++) {
        int x = xg * 4 + xr;
        ull acc2[4][3];
        #pragma unroll
        for (int oo = 0; oo < 4; oo++)
            #pragma unroll
            for (int j = 0; j < 3; j++) acc2[oo][j] = 0ull;

        for (int h = 0; h < Hh; h++) {
            int s = c_shift[h];
            int plen = HT + 2 * s;
            __syncthreads();
            for (int idx = t; idx < Cc * 3 * plen; idx += 256) {
                int c = idx / (3 * plen);
                int rem = idx - c * 3 * plen;
                int r = rem / plen;
                int p = rem - r * plen;
                int xx = x + (r - 1) * s;
                int y = p - s;
                float v = 0.0f;
                if (xx >= 0 && xx < WD && y >= 0 && y < HT)
                    v = cb[((size_t)c * WD + xx) * HT + y];
                insm[c * (3 * W2) + r * W2 + p] = v;
            }
            for (int idx = t; idx < OCH * SDIM; idx += 256)
                W2sm[idx] = (&g_W2[b][h][0][0])[idx];
            __syncthreads();

            int ybase = ty * 6;
            #pragma unroll 1
            for (int c = 0; c < Cc; c++) {
                const float* pc = insm + c * (3 * W2);
                #pragma unroll
                for (int d = 0; d < 9; d++) {
                    const float* px = pc + (d / 3) * W2 + (d % 3) * s + ybase;
                    float w0 = W2sm[(to * 4 + 0) * SDIM + c * 9 + d];
                    float w1 = W2sm[(to * 4 + 1) * SDIM + c * 9 + d];
                    float w2 = W2sm[(to * 4 + 2) * SDIM + c * 9 + d];
                    float w3 = W2sm[(to * 4 + 3) * SDIM + c * 9 + d];
                    ull w0p = pk2(w0, w0), w1p = pk2(w1, w1);
                    ull w2p = pk2(w2, w2), w3p = pk2(w3, w3);
                    #pragma unroll
                    for (int j = 0; j < 3; j++) {
                        ull xv = pk2(px[2 * j], px[2 * j + 1]);
                        acc2[0][j] = ffma2(w0p, xv, acc2[0][j]);
                        acc2[1][j] = ffma2(w1p, xv, acc2[1][j]);
                        acc2[2][j] = ffma2(w2p, xv, acc2[2][j]);
                        acc2[3][j] = ffma2(w3p, xv, acc2[3][j]);
                    }
                }
            }
        }

        #pragma unroll
        for (int oo = 0; oo < 4; oo++) {
            int o = to * 4 + oo;
            float s1 = 0.0f, s2 = 0.0f;
            float* op = out + (((size_t)b * OCH + o) * WD + x) * HT + ty * 6;
            #pragma unroll
            for (int j = 0; j < 3; j++) {
                float lo, hi;
                upk2(acc2[oo][j], lo, hi);
                op[2 * j]     = lo;
                op[2 * j + 1] = hi;
                s1 += lo + hi;
                s2 = fmaf(lo, lo, s2);
                s2 = fmaf(hi, hi, s2);
            }
            #pragma unroll
            for (int off2 = 16; off2 > 0; off2 >>= 1) {
                s1 += __shfl_xor_sync(0xffffffffu, s1, off2);
                s2 += __shfl_xor_sync(0xffffffffu, s2, off2);
            }
            if (ty == 0) {
                atomicAdd(&g_bnsum[o], s1);
                atomicAdd(&g_bnsq[o], s2);
            }
        }
    }
}

// ---------------- kernel 6: batchnorm + ReLU ----------------
__global__ void k_bn(float* __restrict__ out, const float* __restrict__ gamma,
                     const float* __restrict__ beta) {
    __shared__ float ssc[OCH], sbi[OCH];
    if (threadIdx.x < OCH) {
        int o = threadIdx.x;
        float invN = 1.0f / ((float)Bb * NPIX);
        float m = g_bnsum[o] * invN;
        float v = g_bnsq[o] * invN - m * m;
        float sc = gamma[o] * rsqrtf(v + 1e-5f);
        ssc[o] = sc;
        sbi[o] = beta[o] - m * sc;
    }
    __syncthreads();
    size_t total = (size_t)Bb * OCH * NPIX;
    for (size_t i = (size_t)blockIdx.x * blockDim.x + threadIdx.x; i < total;
         i += (size_t)gridDim.x * blockDim.x) {
        int o = (int)((i / NPIX) & 31);
        float v = fmaf(out[i], ssc[o], sbi[o]);
        out[i] = fmaxf(v, 0.0f);
    }
}

// ---------------- launch ----------------
extern "C" void kernel_launch(void* const* d_in, const int* in_sizes, int n_in,
                              void* d_out, int out_size) {
    (void)in_sizes; (void)n_in; (void)out_size;
    const float* cen   = (const float*)d_in[0];
    const float* wq    = (const float*)d_in[1];
    const float* wk    = (const float*)d_in[2];
    const float* wv    = (const float*)d_in[3];
    const float* sum_w = (const float*)d_in[4];
    const float* w_out = (const float*)d_in[5];
    const float* gamma = (const float*)d_in[6];
    const float* beta  = (const float*)d_in[7];
    float* out = (float*)d_out;

    int dynsmem_out  = (Cc * 3 * W2 + OCH * SDIM) * (int)sizeof(float);
    int dynsmem_attn = 46096 * (int)sizeof(float);
    int dynsmem_sb   = 16 * (44 * 40 + 1) * (int)sizeof(float);
    cudaFuncSetAttribute(k_out,        cudaFuncAttributeMaxDynamicSharedMemorySize, dynsmem_out);
    cudaFuncSetAttribute(k_attn,       cudaFuncAttributeMaxDynamicSharedMemorySize, dynsmem_attn);
    cudaFuncSetAttribute(k_stripy_big, cudaFuncAttributeMaxDynamicSharedMemorySize, dynsmem_sb);

    k_prep<<<4, 256>>>(wq, wk, wv, sum_w);
    k_zero<<<512, 256>>>();
    k_corrF<<<dim3(24, 4, 8), 256>>>(cen);
    k_stripx<<<dim3(64, 4, 8), 256>>>(cen);
    k_stripy_small<<<dim3(32, 3, 8), 256>>>(cen);
    k_stripy_big<<<dim3(32, 1, 8), 256, dynsmem_sb>>>(cen);
    k_corner<<<dim3(32, 4, 8), 256>>>(cen);
    k_mirrorF<<<32, 256>>>();
    k_attn<<<32, 512, dynsmem_attn>>>(w_out);
    k_out<<<dim3(48, 8), 256, dynsmem_out>>>(cen, out);
    k_bn<<<2048, 256>>>(out, gamma, beta);
}

// round 14
// speedup vs baseline: 1.1549x; 1.1549x over previous
#include <cuda_runtime.h>
#include <math.h>

#define Bb 8
#define Cc 16
#define WD 192
#define HT 192
#define NPIX (WD*HT)
#define Hh 4
#define HID 16
#define OCH 32
#define W2 214
#define SDIM 144

typedef unsigned long long ull;

// ---------------- packed f32x2 helpers (k_out only) ----------------
__device__ __forceinline__ ull pk2(float lo, float hi) {
    ull u;
    asm("mov.b64 %0, {%1, %2};" : "=l"(u) : "f"(lo), "f"(hi));
    return u;
}
__device__ __forceinline__ void upk2(ull u, float& lo, float& hi) {
    asm("mov.b64 {%0, %1}, %2;" : "=f"(lo), "=f"(hi) : "l"(u));
}
__device__ __forceinline__ ull ffma2(ull a, ull b, ull c) {
    ull d;
    asm("fma.rn.f32x2 %0, %1, %2, %3;" : "=l"(d) : "l"(a), "l"(b), "l"(c));
    return d;
}

// ---------------- device scratch ----------------
__device__ float g_Wq[Hh][HID][SDIM];
__device__ float g_Wk[Hh][128][SDIM];
__device__ float g_Wv[Hh][128][SDIM];
__device__ float g_W2[Bb][Hh][OCH][SDIM];
__device__ float g_bnsum[OCH];
__device__ float g_bnsq[OCH];

// correlation tables: [bh][pair=c1*16+c2][lag dd=ix*5+iy]
__device__ float g_F [32][256][25];
__device__ float g_SxS[2][32][256][25];
__device__ float g_SyS[2][32][256][25];
__device__ float g_Cn [4][32][256][25];

__constant__ int c_shift[4] = {1, 2, 4, 8};
__constant__ int c_off[8]   = {0, 1, 2, 5, 8, 7, 6, 3};

// ---------------- kernel 1: fold blend kernels into effective conv weights ----------------
__global__ void k_prep(const float* __restrict__ wq, const float* __restrict__ wk,
                       const float* __restrict__ wv, const float* __restrict__ sum_w) {
    int h = blockIdx.x;
    int t = threadIdx.x;
    __shared__ float wcen[Cc][9];
    __shared__ float wsur[Cc][8][9];

    if (t < Cc * 9) {
        int c = t / 9, d = t % 9;
        float sw = sum_w[h * Cc + c];
        float su_f = (d == 4) ? 0.125f : (7.0f / 64.0f);
        float ce   = (d == 4) ? 1.0f : 0.0f;
        wcen[c][d] = su_f * (1.0f - sw) + ce * sw;
    }
    for (int idx = t; idx < Cc * 8 * 9; idx += 256) {
        int c = idx / 72;
        int k = (idx / 9) % 8;
        int d = idx % 9;
        float sw = sum_w[h * Cc + c];
        float delta = ((d == 4) ? 1.0f : 0.0f) + ((d == c_off[k]) ? -1.0f : 0.0f);
        float ce    = (d == 4) ? 1.0f : 0.0f;
        float k2w   = (delta - ce) * 1.125f + 0.125f;
        wsur[c][k][d] = delta * (1.0f - sw) + k2w * sw;
    }
    __syncthreads();

    for (int idx = t; idx < HID * SDIM; idx += 256) {
        int q = idx / SDIM, c = (idx % SDIM) / 9, d = idx % 9;
        g_Wq[h][q][c * 9 + d] = wq[(h * HID + q) * Cc + c] * wcen[c][d];
    }
    for (int idx = t; idx < 128 * SDIM; idx += 256) {
        int o = idx / SDIM, c = (idx % SDIM) / 9, d = idx % 9;
        float ak = 0.0f, av = 0.0f;
        #pragma unroll
        for (int k = 0; k < 8; k++) {
            float ws = wsur[c][k][d];
            ak = fmaf(wk[(h * 128 + o) * 128 + k * Cc + c], ws, ak);
            av = fmaf(wv[(h * 128 + o) * 128 + k * Cc + c], ws, av);
        }
        g_Wk[h][o][c * 9 + d] = ak;
        g_Wv[h][o][c * 9 + d] = av;
    }
}

// ---------------- kernel 2: zero accumulators ----------------
__global__ void k_zero() {
    const long per = 32L * 256 * 25;
    long stride = (long)gridDim.x * 256;
    long i0 = (long)blockIdx.x * 256 + threadIdx.x;
    for (long i = i0; i < per; i += stride) (&g_F[0][0][0])[i] = 0.0f;
    for (long i = i0; i < 2 * per; i += stride) (&g_SxS[0][0][0][0])[i] = 0.0f;
    for (long i = i0; i < 2 * per; i += stride) (&g_SyS[0][0][0][0])[i] = 0.0f;
    for (long i = i0; i < 4 * per; i += stride) (&g_Cn[0][0][0][0])[i] = 0.0f;
    if (blockIdx.x == 0 && threadIdx.x < OCH) {
        g_bnsum[threadIdx.x] = 0.0f;
        g_bnsq[threadIdx.x]  = 0.0f;
    }
}

// ---------------- kernel 3a: full-domain correlations F(dd) for dd=12..24 ----------------
// grid (24 x-chunks of 8 rows, Hh, Bb), 256 threads:
//   c2 = t&15, c1-group = (t>>4)&3 (4 c1 each), qy-quarter = t>>6 (48 qy each).
// Register tile: 4 c1 x 13 lags -> 17 LDS per 52 FMA (FMA-bound).
__global__ void __launch_bounds__(256) k_corrF(const float* __restrict__ cen) {
    __shared__ float st[16 * 673];
    int xc = blockIdx.x, h = blockIdx.y, b = blockIdx.z;
    int s = c_shift[h];
    int bh = b * Hh + h;
    int t = threadIdx.x;
    int c2 = t & 15;
    int c1b = ((t >> 4) & 3) * 4;
    int qq = t >> 6;
    const float* cb = cen + (size_t)b * Cc * NPIX;

    float acc[52];
    #pragma unroll
    for (int i = 0; i < 52; i++) acc[i] = 0.0f;

    for (int qx = xc * 8; qx < xc * 8 + 8; qx++) {
        __syncthreads();
        for (int idx = t; idx < 16 * 673; idx += 256) {
            int c = idx / 673;
            int rm = idx - c * 673;
            float v = 0.0f;
            if (rm < 672) {
                int k = rm / 224, j = rm - k * 224;
                int r = qx + k * s;
                int y = j - 16;
                if (r < WD && y >= 0 && y < HT)
                    v = cb[((size_t)c * WD + r) * HT + y];
            }
            st[idx] = v;
        }
        __syncthreads();

        const float* a0 = st + (c1b + 0) * 673 + 16;
        const float* a1 = st + (c1b + 1) * 673 + 16;
        const float* a2 = st + (c1b + 2) * 673 + 16;
        const float* a3 = st + (c1b + 3) * 673 + 16;
        const float* b0 = st + c2 * 673 + 16;
        const float* b1 = b0 + 224;
        const float* b2 = b1 + 224;
        #pragma unroll 2
        for (int qy = qq * 48; qy < qq * 48 + 48; qy++) {
            float av0 = a0[qy], av1 = a1[qy], av2 = a2[qy], av3 = a3[qy];
            float bv;
            #define CORR_LAG(L, EXPR) \
                bv = (EXPR); \
                acc[0 * 13 + (L)] = fmaf(av0, bv, acc[0 * 13 + (L)]); \
                acc[1 * 13 + (L)] = fmaf(av1, bv, acc[1 * 13 + (L)]); \
                acc[2 * 13 + (L)] = fmaf(av2, bv, acc[2 * 13 + (L)]); \
                acc[3 * 13 + (L)] = fmaf(av3, bv, acc[3 * 13 + (L)]);
            CORR_LAG(0,  b0[qy])
            CORR_LAG(1,  b0[qy + s])
            CORR_LAG(2,  b0[qy + 2 * s])
            CORR_LAG(3,  b1[qy - 2 * s])
            CORR_LAG(4,  b1[qy - s])
            CORR_LAG(5,  b1[qy])
            CORR_LAG(6,  b1[qy + s])
            CORR_LAG(7,  b1[qy + 2 * s])
            CORR_LAG(8,  b2[qy - 2 * s])
            CORR_LAG(9,  b2[qy - s])
            CORR_LAG(10, b2[qy])
            CORR_LAG(11, b2[qy + s])
            CORR_LAG(12, b2[qy + 2 * s])
            #undef CORR_LAG
        }
    }
    #pragma unroll
    for (int i = 0; i < 4; i++) {
        float* dst = &g_F[bh][(c1b + i) * 16 + c2][12];
        #pragma unroll
        for (int l = 0; l < 13; l++) atomicAdd(dst + l, acc[i * 13 + l]);
    }
}

// ---------------- kernel 3b: x-border strips ----------------
// grid (64 = side(2) x ychunk(4) x qslot(8), Hh, Bb); ONE fill per block.
__global__ void __launch_bounds__(256) k_stripx(const float* __restrict__ cen) {
    __shared__ float yw[16 * 401];
    int bx = blockIdx.x;
    int side = bx & 1, chunk = (bx >> 1) & 3, qslot = bx >> 3;
    int h = blockIdx.y, b = blockIdx.z;
    int s = c_shift[h];
    if (qslot >= s) return;
    int bh = b * Hh + h;
    int t = threadIdx.x;
    int c1 = t & 15, c2 = t >> 4;
    const float* cb = cen + (size_t)b * Cc * NPIX;
    int x0 = side ? (WD - s) : 0;
    int qx = x0 + qslot;
    int ybase = chunk * 48 - 16;

    for (int idx = t; idx < 16 * 401; idx += 256) {
        int c = idx / 401;
        int rm = idx - c * 401;
        float v = 0.0f;
        if (rm < 400) {
            int k = rm / 80, j = rm - k * 80;
            int r = qx + (k - 2) * s;
            int y = ybase + j;
            if (r >= 0 && r < WD && y >= 0 && y < HT)
                v = cb[((size_t)c * WD + r) * HT + y];
        }
        yw[idx] = v;
    }
    __syncthreads();

    float acc[25];
    #pragma unroll
    for (int i = 0; i < 25; i++) acc[i] = 0.0f;

    const float* ar = yw + c1 * 401 + 2 * 80 + 16;
    const float* bb = yw + c2 * 401 + 16;
    for (int jj = 0; jj < 48; jj++) {
        float a = ar[jj];
        #pragma unroll
        for (int ix = 0; ix < 5; ix++) {
            const float* br = bb + ix * 80 + jj;
            #pragma unroll
            for (int iy = 0; iy < 5; iy++)
                acc[ix * 5 + iy] = fmaf(a, br[(iy - 2) * s], acc[ix * 5 + iy]);
        }
    }
    float* dst = &g_SxS[side][bh][c1 * 16 + c2][0];
    #pragma unroll
    for (int i = 0; i < 25; i++) atomicAdd(dst + i, acc[i]);
}

// ---------------- shared body for y-strips ----------------
__device__ __forceinline__ void stripy_body(const float* __restrict__ cen, float* yw,
                                            int side, int chunk, int h, int b) {
    int s = c_shift[h];
    int bh = b * Hh + h;
    int t = threadIdx.x;
    int c1 = t & 15, c2 = t >> 4;
    const float* cb = cen + (size_t)b * Cc * NPIX;
    int y0 = side ? (HT - s) : 0;
    int jy0 = y0 - 2 * s;
    int qx0 = chunk * 12;
    int rows = 12 + 4 * s;
    int ww = 5 * s;
    int stride = rows * ww + 1;

    for (int idx = t; idx < 16 * stride; idx += 256) {
        int c = idx / stride;
        int rm = idx - c * stride;
        float v = 0.0f;
        if (rm < rows * ww) {
            int rr = rm / ww, j = rm - rr * ww;
            int r = qx0 - 2 * s + rr;
            int y = jy0 + j;
            if (r >= 0 && r < WD && y >= 0 && y < HT)
                v = cb[((size_t)c * WD + r) * HT + y];
        }
        yw[idx] = v;
    }
    __syncthreads();

    float acc[25];
    #pragma unroll
    for (int i = 0; i < 25; i++) acc[i] = 0.0f;

    const float* base1 = yw + c1 * stride;
    const float* base2 = yw + c2 * stride;
    for (int dx = 0; dx < 12; dx++) {
        const float* ar = base1 + (dx + 2 * s) * ww + 2 * s;
        for (int jj = 0; jj < s; jj++) {
            float a = ar[jj];
            #pragma unroll
            for (int ix = 0; ix < 5; ix++) {
                const float* br = base2 + (dx + ix * s) * ww + jj;
                #pragma unroll
                for (int iy = 0; iy < 5; iy++)
                    acc[ix * 5 + iy] = fmaf(a, br[iy * s], acc[ix * 5 + iy]);
            }
        }
    }
    float* dst = &g_SyS[side][bh][c1 * 16 + c2][0];
    #pragma unroll
    for (int i = 0; i < 25; i++) atomicAdd(dst + i, acc[i]);
}

// s<=4 (h=0..2): static smem 16*561 floats = 35.9KB -> high occupancy
__global__ void __launch_bounds__(256) k_stripy_small(const float* __restrict__ cen) {
    __shared__ float yw[16 * 561];
    stripy_body(cen, yw, blockIdx.x & 1, blockIdx.x >> 1, blockIdx.y, blockIdx.z);
}
// s=8 (h=3): dynamic smem 112.7KB
__global__ void __launch_bounds__(256) k_stripy_big(const float* __restrict__ cen) {
    extern __shared__ float yw[];
    stripy_body(cen, yw, blockIdx.x & 1, blockIdx.x >> 1, 3, blockIdx.z);
}

// ---------------- kernel 3d: corner patches ----------------
// grid (32 = corner(4) x islot(8), Hh, Bb); early exit islot>=s; atomicAdd.
__global__ void __launch_bounds__(256) k_corner(const float* __restrict__ cen) {
    int bx = blockIdx.x;
    int corner = bx & 3, islot = bx >> 2;
    int cx = corner >> 1, cy = corner & 1;
    int h = blockIdx.y, b = blockIdx.z;
    int s = c_shift[h];
    if (islot >= s) return;
    int bh = b * Hh + h;
    int t = threadIdx.x;
    int c1 = t & 15, c2 = t >> 4;
    const float* cb = cen + (size_t)b * Cc * NPIX;
    int x0 = cx ? (WD - s) : 0;
    int y0 = cy ? (HT - s) : 0;

    float acc[25];
    #pragma unroll
    for (int i = 0; i < 25; i++) acc[i] = 0.0f;

    int qx = x0 + islot;
    for (int j = 0; j < s; j++) {
        int qy = y0 + j;
        float a = cb[((size_t)c1 * WD + qx) * HT + qy];
        #pragma unroll
        for (int ix = 0; ix < 5; ix++) {
            int bxx = qx + (ix - 2) * s;
            #pragma unroll
            for (int iy = 0; iy < 5; iy++) {
                int by = qy + (iy - 2) * s;
                float bv = (bxx >= 0 && bxx < WD && by >= 0 && by < HT)
                           ? cb[((size_t)c2 * WD + bxx) * HT + by] : 0.0f;
                acc[ix * 5 + iy] = fmaf(a, bv, acc[ix * 5 + iy]);
            }
        }
    }
    float* dst = &g_Cn[corner][bh][c1 * 16 + c2][0];
    #pragma unroll
    for (int i = 0; i < 25; i++) atomicAdd(dst + i, acc[i]);
}

// ---------------- kernel 3e: mirror fill F for dd<12 ----------------
__global__ void k_mirrorF() {
    int bh = blockIdx.x;
    int p = threadIdx.x;
    int cA = p >> 4, cB = p & 15;
    int ps = cB * 16 + cA;
    #pragma unroll
    for (int d = 0; d < 12; d++)
        g_F[bh][p][d] = g_F[bh][ps][24 - d];
}

// ---------------- kernel 4: per (b,h) attention head (assembles S from corr tables) ----------------
__global__ void __launch_bounds__(512) k_attn(const float* __restrict__ w_out) {
    extern __shared__ float pool[];
    float* S_sm  = pool;
    float* Wk_sm = pool + 20880;
    float* Wq_sm = pool + 39440;
    float* T_sm  = pool + 41744;
    float* G     = pool + 44048;
    float* M     = Wk_sm;
    __shared__ float nq[16], nk[128], red[512];

    int bh = blockIdx.x;
    int b = bh >> 2, h = bh & 3;
    int t = threadIdx.x;

    for (int idx = t; idx < SDIM * SDIM; idx += 512) {
        int r = idx / SDIM, c = idx - r * SDIM;
        int c1 = r / 9, d1 = r - c1 * 9;
        int c2 = c / 9, d2 = c - c2 * 9;
        int o1x = d1 / 3 - 1, o1y = d1 % 3 - 1;
        int o2x = d2 / 3 - 1, o2y = d2 % 3 - 1;
        int dd = (o2x - o1x + 2) * 5 + (o2y - o1y + 2);
        int p = c1 * 16 + c2;
        float v = g_F[bh][p][dd];
        if (o1x > 0)      v -= g_SxS[0][bh][p][dd];
        else if (o1x < 0) v -= g_SxS[1][bh][p][dd];
        if (o1y > 0)      v -= g_SyS[0][bh][p][dd];
        else if (o1y < 0) v -= g_SyS[1][bh][p][dd];
        if (o1x != 0 && o1y != 0) {
            int ci = ((o1x > 0) ? 0 : 2) + ((o1y > 0) ? 0 : 1);
            v += g_Cn[ci][bh][p][dd];
        }
        S_sm[r * 145 + c] = v;
    }
    for (int idx = t; idx < 128 * SDIM; idx += 512) {
        int r = idx / SDIM, c = idx - r * SDIM;
        Wk_sm[r * 145 + c] = (&g_Wk[h][0][0])[idx];
    }
    for (int idx = t; idx < 16 * SDIM; idx += 512)
        Wq_sm[idx] = (&g_Wq[h][0][0])[idx];
    __syncthreads();

    for (int g = t; g < 576; g += 512) {
        int q = g / 36, i0 = (g - q * 36) * 4;
        float a0 = 0.0f, a1 = 0.0f, a2 = 0.0f, a3 = 0.0f;
        const float* wqr = Wq_sm + q * SDIM;
        #pragma unroll 4
        for (int j = 0; j < SDIM; j++) {
            float wv = wqr[j];
            const float* sr = S_sm + j * 145 + i0;
            a0 = fmaf(wv, sr[0], a0);
            a1 = fmaf(wv, sr[1], a1);
            a2 = fmaf(wv, sr[2], a2);
            a3 = fmaf(wv, sr[3], a3);
        }
        float* tr = T_sm + q * SDIM + i0;
        tr[0] = a0; tr[1] = a1; tr[2] = a2; tr[3] = a3;
    }
    __syncthreads();

    if (t < 16) {
        float a = 0.0f;
        for (int i = 0; i < SDIM; i++)
            a = fmaf(T_sm[t * SDIM + i], Wq_sm[t * SDIM + i], a);
        nq[t] = fmaxf(sqrtf(fmaxf(a, 0.0f)), 1e-12f);
    }

    {
        int q = t >> 5, k0 = (t & 31) * 4;
        float a0 = 0.0f, a1 = 0.0f, a2 = 0.0f, a3 = 0.0f;
        const float* tq = T_sm + q * SDIM;
        const float* w0 = Wk_sm + (k0 + 0) * 145;
        const float* w1 = Wk_sm + (k0 + 1) * 145;
        const float* w2 = Wk_sm + (k0 + 2) * 145;
        const float* w3 = Wk_sm + (k0 + 3) * 145;
        #pragma unroll 4
        for (int i = 0; i < SDIM; i++) {
            float tv = tq[i];
            a0 = fmaf(tv, w0[i], a0);
            a1 = fmaf(tv, w1[i], a1);
            a2 = fmaf(tv, w2[i], a2);
            a3 = fmaf(tv, w3[i], a3);
        }
        G[q * 128 + k0 + 0] = a0;
        G[q * 128 + k0 + 1] = a1;
        G[q * 128 + k0 + 2] = a2;
        G[q * 128 + k0 + 3] = a3;
    }

    {
        int k = t & 127, g = t >> 7;
        const float* wk_r = Wk_sm + k * 145;
        float a = 0.0f;
        #pragma unroll 1
        for (int qd = 0; qd < 9; qd++) {
            int i0 = g * 36 + qd * 4;
            float r0 = 0.0f, r1 = 0.0f, r2 = 0.0f, r3 = 0.0f;
            const float* s0 = S_sm + (i0 + 0) * 145;
            const float* s1 = S_sm + (i0 + 1) * 145;
            const float* s2 = S_sm + (i0 + 2) * 145;
            const float* s3 = S_sm + (i0 + 3) * 145;
            #pragma unroll 4
            for (int j = 0; j < SDIM; j++) {
                float wv = wk_r[j];
                r0 = fmaf(s0[j], wv, r0);
                r1 = fmaf(s1[j], wv, r1);
                r2 = fmaf(s2[j], wv, r2);
                r3 = fmaf(s3[j], wv, r3);
            }
            a = fmaf(wk_r[i0 + 0], r0, a);
            a = fmaf(wk_r[i0 + 1], r1, a);
            a = fmaf(wk_r[i0 + 2], r2, a);
            a = fmaf(wk_r[i0 + 3], r3, a);
        }
        red[t] = a;
    }
    __syncthreads();
    if (t < 128) {
        float sum = red[t] + red[t + 128] + red[t + 256] + red[t + 384];
        nk[t] = fmaxf(sqrtf(fmaxf(sum, 0.0f)), 1e-12f);
    }
    __syncthreads();

    for (int idx = t; idx < 2048; idx += 512) {
        int q = idx >> 7, k = idx & 127;
        G[idx] = G[idx] / (nq[q] * nk[k] * 192.0f);
    }
    __syncthreads();

    float lsum = 0.0f;
    for (int idx = t; idx < 2048; idx += 512) lsum += G[idx];
    red[t] = lsum; __syncthreads();
    for (int st = 256; st > 0; st >>= 1) { if (t < st) red[t] += red[t + st]; __syncthreads(); }
    float mean = red[0] * (1.0f / 2048.0f);
    __syncthreads();
    float lss = 0.0f;
    for (int idx = t; idx < 2048; idx += 512) { float d = G[idx] - mean; lss = fmaf(d, d, lss); }
    red[t] = lss; __syncthreads();
    for (int st = 256; st > 0; st >>= 1) { if (t < st) red[t] += red[t + st]; __syncthreads(); }
    float var = red[0] * (1.0f / 2048.0f);
    float iscale = rsqrtf(var + 1e-5f);
    __syncthreads();
    for (int idx = t; idx < 2048; idx += 512)
        G[idx] = (G[idx] - mean) * iscale;
    __syncthreads();

    int wid = t >> 5, lane = t & 31;
    {
        int q = wid;
        float m = -1e30f;
        for (int k = lane; k < 128; k += 32) m = fmaxf(m, G[q * 128 + k]);
        #pragma unroll
        for (int o = 16; o > 0; o >>= 1) m = fmaxf(m, __shfl_xor_sync(0xffffffffu, m, o));
        float ssum = 0.0f;
        for (int k = lane; k < 128; k += 32) {
            float e = expf(G[q * 128 + k] - m);
            G[q * 128 + k] = e;
            ssum += e;
        }
        #pragma unroll
        for (int o = 16; o > 0; o >>= 1) ssum += __shfl_xor_sync(0xffffffffu, ssum, o);
        float inv = 1.0f / ssum;
        for (int k = lane; k < 128; k += 32) G[q * 128 + k] *= inv;
    }
    __syncthreads();

    float mv[8];
    {
        #pragma unroll
        for (int r = 0; r < 8; r++) {
            int idx = t + r * 512;
            int o = idx >> 7, k = idx & 127;
            float a = 0.0f;
            #pragma unroll
            for (int q = 0; q < 16; q++)
                a = fmaf(w_out[o * 64 + h * 16 + q], G[q * 128 + k], a);
            mv[r] = a;
        }
    }
    __syncthreads();
    #pragma unroll
    for (int r = 0; r < 8; r++) M[t + r * 512] = mv[r];
    __syncthreads();

    for (int g = t; g < OCH * 36; g += 512) {
        int o = g / 36, i0 = (g - o * 36) * 4;
        float a0 = 0.0f, a1 = 0.0f, a2 = 0.0f, a3 = 0.0f;
        const float* mo = M + o * 128;
        #pragma unroll 4
        for (int k = 0; k < 128; k++) {
            float mvv = mo[k];
            const float* wvr = &g_Wv[h][k][i0];
            a0 = fmaf(mvv, wvr[0], a0);
            a1 = fmaf(mvv, wvr[1], a1);
            a2 = fmaf(mvv, wvr[2], a2);
            a3 = fmaf(mvv, wvr[3], a3);
        }
        float* w2r = &g_W2[b][h][o][i0];
        w2r[0] = a0; w2r[1] = a1; w2r[2] = a2; w2r[3] = a3;
    }
}

// ---------------- kernel 5: fused output conv (f32x2) + BN stats ----------------
// grid (96 x-groups of 2 rows, Bb), 256 threads = 8 warps (o-groups of 4) x 32 lanes (y-groups of 6)
__global__ void __launch_bounds__(256) k_out(const float* __restrict__ cen, float* __restrict__ out) {
    extern __shared__ float dsm[];
    float* insm = dsm;
    float* W2sm = dsm + Cc * 3 * W2;

    int xg = blockIdx.x, b = blockIdx.y;
    int t = threadIdx.x;
    int ty = t & 31, to = t >> 5;
    const float* cb = cen + (size_t)b * Cc * NPIX;

    for (int xr = 0; xr < 2; xr++) {
        int x = xg * 2 + xr;
        ull acc2[4][3];
        #pragma unroll
        for (int oo = 0; oo < 4; oo++)
            #pragma unroll
            for (int j = 0; j < 3; j++) acc2[oo][j] = 0ull;

        for (int h = 0; h < Hh; h++) {
            int s = c_shift[h];
            int plen = HT + 2 * s;
            __syncthreads();
            for (int idx = t; idx < Cc * 3 * plen; idx += 256) {
                int c = idx / (3 * plen);
                int rem = idx - c * 3 * plen;
                int r = rem / plen;
                int p = rem - r * plen;
                int xx = x + (r - 1) * s;
                int y = p - s;
                float v = 0.0f;
                if (xx >= 0 && xx < WD && y >= 0 && y < HT)
                    v = cb[((size_t)c * WD + xx) * HT + y];
                insm[c * (3 * W2) + r * W2 + p] = v;
            }
            for (int idx = t; idx < OCH * SDIM; idx += 256)
                W2sm[idx] = (&g_W2[b][h][0][0])[idx];
            __syncthreads();

            int ybase = ty * 6;
            #pragma unroll 1
            for (int c = 0; c < Cc; c++) {
                const float* pc = insm + c * (3 * W2);
                #pragma unroll
                for (int d = 0; d < 9; d++) {
                    const float* px = pc + (d / 3) * W2 + (d % 3) * s + ybase;
                    float w0 = W2sm[(to * 4 + 0) * SDIM + c * 9 + d];
                    float w1 = W2sm[(to * 4 + 1) * SDIM + c * 9 + d];
                    float w2 = W2sm[(to * 4 + 2) * SDIM + c * 9 + d];
                    float w3 = W2sm[(to * 4 + 3) * SDIM + c * 9 + d];
                    ull w0p = pk2(w0, w0), w1p = pk2(w1, w1);
                    ull w2p = pk2(w2, w2), w3p = pk2(w3, w3);
                    #pragma unroll
                    for (int j = 0; j < 3; j++) {
                        ull xv = pk2(px[2 * j], px[2 * j + 1]);
                        acc2[0][j] = ffma2(w0p, xv, acc2[0][j]);
                        acc2[1][j] = ffma2(w1p, xv, acc2[1][j]);
                        acc2[2][j] = ffma2(w2p, xv, acc2[2][j]);
                        acc2[3][j] = ffma2(w3p, xv, acc2[3][j]);
                    }
                }
            }
        }

        #pragma unroll
        for (int oo = 0; oo < 4; oo++) {
            int o = to * 4 + oo;
            float s1 = 0.0f, s2 = 0.0f;
            float* op = out + (((size_t)b * OCH + o) * WD + x) * HT + ty * 6;
            #pragma unroll
            for (int j = 0; j < 3; j++) {
                float lo, hi;
                upk2(acc2[oo][j], lo, hi);
                op[2 * j]     = lo;
                op[2 * j + 1] = hi;
                s1 += lo + hi;
                s2 = fmaf(lo, lo, s2);
                s2 = fmaf(hi, hi, s2);
            }
            #pragma unroll
            for (int off2 = 16; off2 > 0; off2 >>= 1) {
                s1 += __shfl_xor_sync(0xffffffffu, s1, off2);
                s2 += __shfl_xor_sync(0xffffffffu, s2, off2);
            }
            if (ty == 0) {
                atomicAdd(&g_bnsum[o], s1);
                atomicAdd(&g_bnsq[o], s2);
            }
        }
    }
}

// ---------------- kernel 6: batchnorm + ReLU ----------------
__global__ void k_bn(float* __restrict__ out, const float* __restrict__ gamma,
                     const float* __restrict__ beta) {
    __shared__ float ssc[OCH], sbi[OCH];
    if (threadIdx.x < OCH) {
        int o = threadIdx.x;
        float invN = 1.0f / ((float)Bb * NPIX);
        float m = g_bnsum[o] * invN;
        float v = g_bnsq[o] * invN - m * m;
        float sc = gamma[o] * rsqrtf(v + 1e-5f);
        ssc[o] = sc;
        sbi[o] = beta[o] - m * sc;
    }
    __syncthreads();
    size_t total = (size_t)Bb * OCH * NPIX;
    for (size_t i = (size_t)blockIdx.x * blockDim.x + threadIdx.x; i < total;
         i += (size_t)gridDim.x * blockDim.x) {
        int o = (int)((i / NPIX) & 31);
        float v = fmaf(out[i], ssc[o], sbi[o]);
        out[i] = fmaxf(v, 0.0f);
    }
}

// ---------------- launch ----------------
extern "C" void kernel_launch(void* const* d_in, const int* in_sizes, int n_in,
                              void* d_out, int out_size) {
    (void)in_sizes; (void)n_in; (void)out_size;
    const float* cen   = (const float*)d_in[0];
    const float* wq    = (const float*)d_in[1];
    const float* wk    = (const float*)d_in[2];
    const float* wv    = (const float*)d_in[3];
    const float* sum_w = (const float*)d_in[4];
    const float* w_out = (const float*)d_in[5];
    const float* gamma = (const float*)d_in[6];
    const float* beta  = (const float*)d_in[7];
    float* out = (float*)d_out;

    int dynsmem_out  = (Cc * 3 * W2 + OCH * SDIM) * (int)sizeof(float);
    int dynsmem_attn = 46096 * (int)sizeof(float);
    int dynsmem_sb   = 16 * (44 * 40 + 1) * (int)sizeof(float);
    cudaFuncSetAttribute(k_out,        cudaFuncAttributeMaxDynamicSharedMemorySize, dynsmem_out);
    cudaFuncSetAttribute(k_attn,       cudaFuncAttributeMaxDynamicSharedMemorySize, dynsmem_attn);
    cudaFuncSetAttribute(k_stripy_big, cudaFuncAttributeMaxDynamicSharedMemorySize, dynsmem_sb);

    k_prep<<<4, 256>>>(wq, wk, wv, sum_w);
    k_zero<<<512, 256>>>();
    k_corrF<<<dim3(24, 4, 8), 256>>>(cen);
    k_stripx<<<dim3(64, 4, 8), 256>>>(cen);
    k_stripy_small<<<dim3(32, 3, 8), 256>>>(cen);
    k_stripy_big<<<dim3(32, 1, 8), 256, dynsmem_sb>>>(cen);
    k_corner<<<dim3(32, 4, 8), 256>>>(cen);
    k_mirrorF<<<32, 256>>>();
    k_attn<<<32, 512, dynsmem_attn>>>(w_out);
    k_out<<<dim3(96, 8), 256, dynsmem_out>>>(cen, out);
    k_bn<<<2048, 256>>>(out, gamma, beta);
}